// round 6
// baseline (speedup 1.0000x reference)
#include <cuda_runtime.h>
#include <cuda_bf16.h>
#include <cstdint>

// Problem constants (fixed by the reference: B=4, N=4096, C=256)
#define BB 4
#define NN 4096
#define CC 256
#define M_TOT (BB * NN)          // 16384 rows
#define LN_EPS 1e-6f

// ---------------------------------------------------------------------------
// Scratch (static device globals; no runtime allocation allowed)
// ---------------------------------------------------------------------------
__device__ __align__(16) __nv_bfloat16 g_BhT[CC * CC]; // [n][k] = hi(Wvo[k][n])
__device__ __align__(16) __nv_bfloat16 g_BlT[CC * CC]; // [n][k] = lo(Wvo[k][n])
__device__ __align__(16) __nv_bfloat16 g_Ah[(size_t)M_TOT * CC]; // hi(X) [row][k]
__device__ __align__(16) __nv_bfloat16 g_Al[(size_t)M_TOT * CC]; // lo(X)
__device__ float g_z[(size_t)M_TOT * CC];   // pre-LN activations (16.8 MB)
__device__ float g_psum[256 * CC];          // per-(64-row warp-tile) column sums
__device__ float g_psq [256 * CC];
__device__ float g_mean[BB * CC];
__device__ float g_inv[BB * CC];            // rsqrt(var + eps)

// ---------------------------------------------------------------------------
// Warp-MMA + cp.async helpers (sm_80-era PTX: compiles at compute_103)
// ---------------------------------------------------------------------------
__device__ __forceinline__ uint32_t smem_u32(const void* p) {
    uint32_t a;
    asm("{ .reg .u64 t; cvta.to.shared.u64 t, %1; cvt.u32.u64 %0, t; }" : "=r"(a) : "l"(p));
    return a;
}
#define LDMX4(r, a) \
    asm volatile("ldmatrix.sync.aligned.m8n8.x4.shared.b16 {%0,%1,%2,%3}, [%4];" \
        : "=r"((r)[0]), "=r"((r)[1]), "=r"((r)[2]), "=r"((r)[3]) : "r"(a))
#define LDMX2(r, a) \
    asm volatile("ldmatrix.sync.aligned.m8n8.x2.shared.b16 {%0,%1}, [%2];" \
        : "=r"((r)[0]), "=r"((r)[1]) : "r"(a))
#define MMA16816(c, a, b) \
    asm volatile("mma.sync.aligned.m16n8k16.row.col.f32.bf16.bf16.f32 " \
        "{%0,%1,%2,%3}, {%4,%5,%6,%7}, {%8,%9}, {%0,%1,%2,%3};" \
        : "+f"((c)[0]), "+f"((c)[1]), "+f"((c)[2]), "+f"((c)[3]) \
        : "r"((a)[0]), "r"((a)[1]), "r"((a)[2]), "r"((a)[3]), "r"((b)[0]), "r"((b)[1]))
#define CP16(dst, src) \
    asm volatile("cp.async.cg.shared.global [%0], [%1], 16;" :: "r"(dst), "l"(src))
#define CP_COMMIT() asm volatile("cp.async.commit_group;" ::: "memory")
#define CP_WAIT(n)  asm volatile("cp.async.wait_group %0;" :: "n"(n) : "memory")

// Split 8 fp32 into hi/lo bf16, packed 8 x bf16 per uint4.
__device__ __forceinline__ void split8(float4 a, float4 b, uint4& hi, uint4& lo) {
    float f[8] = {a.x, a.y, a.z, a.w, b.x, b.y, b.z, b.w};
    uint32_t h[8], l[8];
#pragma unroll
    for (int j = 0; j < 8; ++j) {
        __nv_bfloat16 bh = __float2bfloat16_rn(f[j]);
        float r = f[j] - __bfloat162float(bh);
        __nv_bfloat16 bl = __float2bfloat16_rn(r);
        h[j] = (uint32_t)__bfloat16_as_ushort(bh);
        l[j] = (uint32_t)__bfloat16_as_ushort(bl);
    }
    hi = make_uint4(h[0] | (h[1] << 16), h[2] | (h[3] << 16), h[4] | (h[5] << 16), h[6] | (h[7] << 16));
    lo = make_uint4(l[0] | (l[1] << 16), l[2] | (l[3] << 16), l[4] | (l[5] << 16), l[6] | (l[7] << 16));
}

// ---------------------------------------------------------------------------
// Kernel 1: fold weights Wvo = Wv @ Wo, split bf16 hi/lo, store TRANSPOSED
// [n][k] (K-major). Biases cancel in the points-axis LayerNorm (dead).
// ---------------------------------------------------------------------------
__global__ void k_prep(const float* __restrict__ Wv, const float* __restrict__ Wo) {
    const int i = blockIdx.x;     // k index (row of Wvo)
    const int j = threadIdx.x;    // n index (col of Wvo)
    float acc = 0.f;
#pragma unroll 8
    for (int m = 0; m < CC; ++m)
        acc += Wv[i * CC + m] * Wo[m * CC + j];
    __nv_bfloat16 h = __float2bfloat16_rn(acc);
    float r = acc - __bfloat162float(h);
    g_BhT[j * CC + i] = h;
    g_BlT[j * CC + i] = __float2bfloat16_rn(r);
}

// ---------------------------------------------------------------------------
// Kernel 1b: split X fp32 -> bf16 hi/lo (row-major [row][k]).
// Keeps the GEMM mainloop free of conversion math and prefetch registers.
// ---------------------------------------------------------------------------
__global__ void __launch_bounds__(256)
k_splitA(const float* __restrict__ X) {
    const int idx = blockIdx.x * blockDim.x + threadIdx.x;   // 8 floats each
    const float4* xp = (const float4*)X + (size_t)idx * 2;
    float4 a = xp[0], b = xp[1];
    uint4 hi, lo;
    split8(a, b, hi, lo);
    ((uint4*)g_Ah)[idx] = hi;
    ((uint4*)g_Al)[idx] = lo;
}

// ---------------------------------------------------------------------------
// Kernel 2: bf16-split warp-MMA GEMM  z = X[16384,256] @ Wvo[256,256]
// 128 CTAs x 256 thr; CTA tile 128m x 256n; warp tile 64x64.
// K in 4 chunks of 64; A and B both pre-split bf16 in gmem, streamed via
// cp.async, double-buffered (2 stages x 96KB = 192KB smem).
// Passes AhBh + AlBh + AhBl accumulate fp32 fragments. Fused per-warp
// deterministic column stats.
// ---------------------------------------------------------------------------
#define SM_AH(s) ((s) * 32768)
#define SM_AL(s) ((s) * 32768 + 16384)
#define SM_BH(s) (65536 + (s) * 65536)
#define SM_BL(s) (65536 + (s) * 65536 + 32768)
#define SMEM_TOTAL 196608

__global__ void __launch_bounds__(256, 1)
k_gemm_mma(const float* __restrict__ X) {
    extern __shared__ char smem[];
    const uint32_t sb = smem_u32(smem);
    const int tid = threadIdx.x;
    const int lane = tid & 31;
    const int warp = tid >> 5;
    const int warp_m = warp & 1;       // 2 warps along m (64 each)
    const int warp_n = warp >> 1;      // 4 warps along n (64 each)
    const int rowBase = blockIdx.x * 128;

    float c[4][8][4];
#pragma unroll
    for (int mi = 0; mi < 4; ++mi)
#pragma unroll
        for (int ni = 0; ni < 8; ++ni)
#pragma unroll
            for (int e = 0; e < 4; ++e) c[mi][ni][e] = 0.f;

    // A tile load: 128 rows x 64 k (128B/row) per array; 4 x 16B per thread.
    auto loadA = [&](int stage, int kc) {
        const char* ah = (const char*)g_Ah + ((size_t)rowBase * CC + kc * 64) * 2;
        const char* al = (const char*)g_Al + ((size_t)rowBase * CC + kc * 64) * 2;
#pragma unroll
        for (int g = 0; g < 4; ++g) {
            const int id = tid * 4 + g;
            const int row = id >> 3;
            const int seg = id & 7;
            uint32_t sw = ((uint32_t)(row * 128 + seg * 16)) ^ (((uint32_t)(row & 7)) << 4);
            const size_t go = (size_t)row * 512 + seg * 16;
            CP16(sb + SM_AH(stage) + sw, ah + go);
            CP16(sb + SM_AL(stage) + sw, al + go);
        }
    };
    // B tile load: 256 n-rows x 64 k; 8 x 16B per thread per array.
    auto loadB = [&](int stage, int kc) {
        const char* bh = (const char*)g_BhT + (size_t)tid * 512 + kc * 128;
        const char* bl = (const char*)g_BlT + (size_t)tid * 512 + kc * 128;
        const uint32_t rsw = ((uint32_t)(tid & 7)) << 4;
#pragma unroll
        for (int g = 0; g < 8; ++g) {
            uint32_t sw = ((uint32_t)(tid * 128 + g * 16)) ^ rsw;
            CP16(sb + SM_BH(stage) + sw, bh + g * 16);
            CP16(sb + SM_BL(stage) + sw, bl + g * 16);
        }
    };

    // ---- prologue: stages 0 and 1 in flight ----
    loadA(0, 0); loadB(0, 0); CP_COMMIT();
    loadA(1, 1); loadB(1, 1); CP_COMMIT();
    CP_WAIT(1);
    __syncthreads();

    // ldmatrix address components
    const int arow = warp_m * 64 + (lane & 15);
    const uint32_t acb = (uint32_t)((lane >> 4) << 4);
    const int brow0 = warp_n * 64 + (lane & 7);
    const uint32_t bcb = (uint32_t)(((lane >> 3) & 1) << 4);

#pragma unroll
    for (int kc = 0; kc < 4; ++kc) {
        const int s = kc & 1;
        const uint32_t AH = sb + SM_AH(s), AL = sb + SM_AL(s);
        const uint32_t BH = sb + SM_BH(s), BL = sb + SM_BL(s);

#pragma unroll
        for (int ks = 0; ks < 4; ++ks) {
            const uint32_t kbyte = (uint32_t)(ks * 32);
            uint32_t ah[4][4], al[4][4];
#pragma unroll
            for (int mi = 0; mi < 4; ++mi) {
                const int r = arow + mi * 16;
                uint32_t sw = ((uint32_t)(r * 128) + kbyte + acb) ^ (((uint32_t)(r & 7)) << 4);
                LDMX4(ah[mi], AH + sw);
                LDMX4(al[mi], AL + sw);
            }
            uint32_t b[8][2];
#pragma unroll
            for (int ni = 0; ni < 8; ++ni) {
                const int r = brow0 + ni * 8;
                uint32_t sw = ((uint32_t)(r * 128) + kbyte + bcb) ^ (((uint32_t)(r & 7)) << 4);
                LDMX2(b[ni], BH + sw);
            }
#pragma unroll
            for (int mi = 0; mi < 4; ++mi)
#pragma unroll
                for (int ni = 0; ni < 8; ++ni)
                    MMA16816(c[mi][ni], ah[mi], b[ni]);
#pragma unroll
            for (int mi = 0; mi < 4; ++mi)
#pragma unroll
                for (int ni = 0; ni < 8; ++ni)
                    MMA16816(c[mi][ni], al[mi], b[ni]);
#pragma unroll
            for (int ni = 0; ni < 8; ++ni) {
                const int r = brow0 + ni * 8;
                uint32_t sw = ((uint32_t)(r * 128) + kbyte + bcb) ^ (((uint32_t)(r & 7)) << 4);
                LDMX2(b[ni], BL + sw);
            }
#pragma unroll
            for (int mi = 0; mi < 4; ++mi)
#pragma unroll
                for (int ni = 0; ni < 8; ++ni)
                    MMA16816(c[mi][ni], ah[mi], b[ni]);
        }

        if (kc < 3) {
            __syncthreads();                       // done reading stage s
            if (kc < 2) {
                loadA(s, kc + 2); loadB(s, kc + 2); CP_COMMIT();
                CP_WAIT(1);                        // next stage's data arrived
            } else {
                CP_WAIT(0);
            }
            __syncthreads();
        }
    }

    // ---- epilogue: store z + deterministic fused column stats ----
    const int gr = lane >> 2;
    const int qc = (lane & 3) * 2;
    const int mW = rowBase + warp_m * 64;
    const int nW = warp_n * 64;
    const int prow = blockIdx.x * 2 + warp_m;

#pragma unroll
    for (int ni = 0; ni < 8; ++ni) {
        float s0 = 0.f, s1 = 0.f, q0 = 0.f, q1 = 0.f;
        const int n0 = nW + ni * 8 + qc;
#pragma unroll
        for (int mi = 0; mi < 4; ++mi) {
            const float* cf = c[mi][ni];
            const int m0 = mW + mi * 16 + gr;
            *(float2*)(g_z + (size_t)m0 * CC + n0)       = make_float2(cf[0], cf[1]);
            *(float2*)(g_z + (size_t)(m0 + 8) * CC + n0) = make_float2(cf[2], cf[3]);
            s0 += cf[0] + cf[2];
            s1 += cf[1] + cf[3];
            q0 += cf[0] * cf[0] + cf[2] * cf[2];
            q1 += cf[1] * cf[1] + cf[3] * cf[3];
        }
#pragma unroll
        for (int off = 4; off < 32; off <<= 1) {
            s0 += __shfl_xor_sync(0xFFFFFFFFu, s0, off);
            s1 += __shfl_xor_sync(0xFFFFFFFFu, s1, off);
            q0 += __shfl_xor_sync(0xFFFFFFFFu, q0, off);
            q1 += __shfl_xor_sync(0xFFFFFFFFu, q1, off);
        }
        if (lane < 4) {
            g_psum[prow * CC + n0]     = s0;
            g_psum[prow * CC + n0 + 1] = s1;
            g_psq [prow * CC + n0]     = q0;
            g_psq [prow * CC + n0 + 1] = q1;
        }
    }
}

// ---------------------------------------------------------------------------
// Kernel 3: finalize mean / inv-std per (batch, channel) from 64 partials
// ---------------------------------------------------------------------------
__global__ void k_finalize() {
    const int b = blockIdx.x;
    const int c = threadIdx.x;
    float s = 0.f, s2 = 0.f;
#pragma unroll 8
    for (int p = 0; p < 64; ++p) {
        s  += g_psum[(b * 64 + p) * CC + c];
        s2 += g_psq [(b * 64 + p) * CC + c];
    }
    const float mean = s * (1.f / NN);
    const float var  = s2 * (1.f / NN) - mean * mean;
    g_mean[b * CC + c] = mean;
    g_inv [b * CC + c] = rsqrtf(var + LN_EPS);
}

// ---------------------------------------------------------------------------
// Kernel 4: epilogue  out = relu((z-mean)*inv*scale + bias) + x  (flat grid)
// ---------------------------------------------------------------------------
__global__ void __launch_bounds__(256)
k_epi(const float* __restrict__ X, const float* __restrict__ scale,
      const float* __restrict__ bias, float* __restrict__ out) {
    const int idx = blockIdx.x * blockDim.x + threadIdx.x;   // float4 index
    const int c4  = idx & 63;
    const int row = idx >> 6;
    const int b   = row >> 12;

    float4 z  = ((const float4*)g_z)[idx];
    float4 x  = ((const float4*)X)[idx];
    float4 mn = ((const float4*)(g_mean + b * CC))[c4];
    float4 iv = ((const float4*)(g_inv  + b * CC))[c4];
    float4 sc = ((const float4*)scale)[c4];
    float4 bi = ((const float4*)bias)[c4];

    float4 o;
    o.x = fmaxf((z.x - mn.x) * iv.x * sc.x + bi.x, 0.f) + x.x;
    o.y = fmaxf((z.y - mn.y) * iv.y * sc.y + bi.y, 0.f) + x.y;
    o.z = fmaxf((z.z - mn.z) * iv.z * sc.z + bi.z, 0.f) + x.z;
    o.w = fmaxf((z.w - mn.w) * iv.w * sc.w + bi.w, 0.f) + x.w;
    ((float4*)out)[idx] = o;
}

// ---------------------------------------------------------------------------
// Inputs: 0=inputs 1=mask 2=Wq 3=bq 4=Wk 5=bk 6=Wv 7=bv 8=Wo 9=bo
//         10=ln_scale 11=ln_bias
// mask/Wq/bq/Wk/bk numerically irrelevant (softmax column-sum collapse);
// bv/bo cancel in the points-axis LayerNorm. All dead.
// ---------------------------------------------------------------------------
extern "C" void kernel_launch(void* const* d_in, const int* in_sizes, int n_in,
                              void* d_out, int out_size) {
    const float* x        = (const float*)d_in[0];
    const float* Wv       = (const float*)d_in[6];
    const float* Wo       = (const float*)d_in[8];
    const float* ln_scale = (const float*)d_in[10];
    const float* ln_bias  = (const float*)d_in[11];
    float* out = (float*)d_out;

    cudaFuncSetAttribute(k_gemm_mma, cudaFuncAttributeMaxDynamicSharedMemorySize, SMEM_TOTAL);

    k_prep<<<CC, CC>>>(Wv, Wo);
    k_splitA<<<(M_TOT * CC / 8) / 256, 256>>>(x);
    k_gemm_mma<<<M_TOT / 128, 256, SMEM_TOTAL>>>(x);
    k_finalize<<<BB, CC>>>();
    k_epi<<<(M_TOT * CC / 4) / 256, 256>>>(x, ln_scale, ln_bias, out);
}

// round 7
// speedup vs baseline: 1.3355x; 1.3355x over previous
#include <cuda_runtime.h>
#include <cuda_fp16.h>
#include <cstdint>

// Problem constants (fixed by the reference: B=4, N=4096, C=256)
#define BB 4
#define NN 4096
#define CC 256
#define M_TOT (BB * NN)          // 16384 rows
#define LN_EPS 1e-6f

// ---------------------------------------------------------------------------
// Scratch (static device globals; no runtime allocation allowed)
// ---------------------------------------------------------------------------
__device__ __align__(16) __half g_BT[CC * CC];   // [n][k] = fp16(Wvo[k][n])
__device__ float g_z[(size_t)M_TOT * CC];        // pre-LN activations (16.8 MB)
__device__ float g_psum[256 * CC];               // per-(64-row warp-tile) col sums
__device__ float g_psq [256 * CC];
__device__ float g_mean[BB * CC];
__device__ float g_inv[BB * CC];                 // rsqrt(var + eps)

// ---------------------------------------------------------------------------
// Warp-MMA + cp.async helpers (sm_80-era PTX: compiles at compute_103)
// ---------------------------------------------------------------------------
__device__ __forceinline__ uint32_t smem_u32(const void* p) {
    uint32_t a;
    asm("{ .reg .u64 t; cvta.to.shared.u64 t, %1; cvt.u32.u64 %0, t; }" : "=r"(a) : "l"(p));
    return a;
}
#define LDMX4(r, a) \
    asm volatile("ldmatrix.sync.aligned.m8n8.x4.shared.b16 {%0,%1,%2,%3}, [%4];" \
        : "=r"((r)[0]), "=r"((r)[1]), "=r"((r)[2]), "=r"((r)[3]) : "r"(a))
#define LDMX2(r, a) \
    asm volatile("ldmatrix.sync.aligned.m8n8.x2.shared.b16 {%0,%1}, [%2];" \
        : "=r"((r)[0]), "=r"((r)[1]) : "r"(a))
#define MMA16816H(c, a, b) \
    asm volatile("mma.sync.aligned.m16n8k16.row.col.f32.f16.f16.f32 " \
        "{%0,%1,%2,%3}, {%4,%5,%6,%7}, {%8,%9}, {%0,%1,%2,%3};" \
        : "+f"((c)[0]), "+f"((c)[1]), "+f"((c)[2]), "+f"((c)[3]) \
        : "r"((a)[0]), "r"((a)[1]), "r"((a)[2]), "r"((a)[3]), "r"((b)[0]), "r"((b)[1]))
#define CP16(dst, src) \
    asm volatile("cp.async.cg.shared.global [%0], [%1], 16;" :: "r"(dst), "l"(src))
#define CP_COMMIT() asm volatile("cp.async.commit_group;" ::: "memory")
#define CP_WAIT(n)  asm volatile("cp.async.wait_group %0;" :: "n"(n) : "memory")

// Split 8 fp32 into hi/lo fp16, packed 8 x fp16 per uint4.
__device__ __forceinline__ void split8h(float4 a, float4 b, uint4& hi, uint4& lo) {
    float f[8] = {a.x, a.y, a.z, a.w, b.x, b.y, b.z, b.w};
    uint32_t h[8], l[8];
#pragma unroll
    for (int j = 0; j < 8; ++j) {
        __half hh = __float2half_rn(f[j]);
        float r = f[j] - __half2float(hh);
        __half hl = __float2half_rn(r);
        h[j] = (uint32_t)__half_as_ushort(hh);
        l[j] = (uint32_t)__half_as_ushort(hl);
    }
    hi = make_uint4(h[0] | (h[1] << 16), h[2] | (h[3] << 16), h[4] | (h[5] << 16), h[6] | (h[7] << 16));
    lo = make_uint4(l[0] | (l[1] << 16), l[2] | (l[3] << 16), l[4] | (l[5] << 16), l[6] | (l[7] << 16));
}

// ---------------------------------------------------------------------------
// Kernel 1: fold weights Wvo = Wv @ Wo -> fp16, store TRANSPOSED [n][k]
// (col-major B operand for mma.row.col). Biases cancel in the points-axis
// LayerNorm and are dead.
// ---------------------------------------------------------------------------
__global__ void k_prep(const float* __restrict__ Wv, const float* __restrict__ Wo) {
    const int i = blockIdx.x;     // k index (row of Wvo)
    const int j = threadIdx.x;    // n index (col of Wvo)
    float acc = 0.f;
#pragma unroll 8
    for (int m = 0; m < CC; ++m)
        acc += Wv[i * CC + m] * Wo[m * CC + j];
    g_BT[j * CC + i] = __float2half_rn(acc);
}

// ---------------------------------------------------------------------------
// Kernel 2: fp16 2-pass split GEMM  z = X[16384,256] @ Wvo[256,256]
// 128 CTAs x 256 thr; CTA tile 128m x 256n; warp tile 64x64.
// A = Ah + Al (fp16 split, 2^-22 residual), B single fp16 (2^-12 trunc).
// z = Ah*B + Al*B, fp32 accumulate. K in 4 chunks of 64, double-buffered:
// B streamed via cp.async; next A chunk prefetched into registers during
// compute, split->STS in the inter-chunk window. Fused per-warp column stats.
// smem = 2 stages x (Ah 16K + Al 16K + B 32K) = 128 KB.
// ---------------------------------------------------------------------------
#define SM_AH(s) ((s) * 65536)
#define SM_AL(s) ((s) * 65536 + 16384)
#define SM_B(s)  ((s) * 65536 + 32768)
#define SMEM_TOTAL 131072

__global__ void __launch_bounds__(256, 1)
k_gemm_mma(const float* __restrict__ X) {
    extern __shared__ char smem[];
    const uint32_t sb = smem_u32(smem);
    const int tid = threadIdx.x;
    const int lane = tid & 31;
    const int warp = tid >> 5;
    const int warp_m = warp & 1;       // 2 warps along m (64 each)
    const int warp_n = warp >> 1;      // 4 warps along n (64 each)
    const int rowBase = blockIdx.x * 128;

    // A-load mapping: 2 threads per row, 32 fp32 each (8 float4)
    const int a_ldrow = tid >> 1;
    const int a_ldch  = (tid & 1) * 32;

    float c[4][8][4];
#pragma unroll
    for (int mi = 0; mi < 4; ++mi)
#pragma unroll
        for (int ni = 0; ni < 8; ++ni)
#pragma unroll
            for (int e = 0; e < 4; ++e) c[mi][ni][e] = 0.f;

    // B tile load: 256 n-rows x 64 k (128B/row); 8 x 16B per thread.
    auto loadB = [&](int stage, int kc) {
        const char* bp = (const char*)g_BT + (size_t)tid * 512 + kc * 128;
        const uint32_t rsw = ((uint32_t)(tid & 7)) << 4;
#pragma unroll
        for (int g = 0; g < 8; ++g) {
            uint32_t sw = ((uint32_t)(tid * 128 + g * 16)) ^ rsw;
            CP16(sb + SM_B(stage) + sw, bp + g * 16);
        }
        CP_COMMIT();
    };
    auto loadAreg = [&](int kc, float4* xr) {
        const float4* xp = (const float4*)(X + (size_t)(rowBase + a_ldrow) * CC + kc * 64 + a_ldch);
#pragma unroll
        for (int g = 0; g < 8; ++g) xr[g] = xp[g];
    };
    auto splitA = [&](int stage, const float4* xr) {
        const uint32_t rsw = ((uint32_t)(a_ldrow & 7)) << 4;
#pragma unroll
        for (int g = 0; g < 4; ++g) {
            uint4 hi, lo;
            split8h(xr[2 * g], xr[2 * g + 1], hi, lo);
            uint32_t sw = ((uint32_t)(a_ldrow * 128 + (a_ldch + g * 8) * 2)) ^ rsw;
            *(uint4*)(smem + SM_AH(stage) + sw) = hi;
            *(uint4*)(smem + SM_AL(stage) + sw) = lo;
        }
    };

    // ---- prologue: B0,B1 in flight; A0 split to smem; A1 in regs ----
    float4 xr[8];
    loadB(0, 0);
    loadB(1, 1);
    loadAreg(0, xr);
    splitA(0, xr);
    loadAreg(1, xr);
    CP_WAIT(1);            // B0 arrived
    __syncthreads();

    // ldmatrix address components
    const int arow = warp_m * 64 + (lane & 15);
    const uint32_t acb = (uint32_t)((lane >> 4) << 4);
    const int brow0 = warp_n * 64 + (lane & 7);
    const uint32_t bcb = (uint32_t)(((lane >> 3) & 1) << 4);

#pragma unroll
    for (int kc = 0; kc < 4; ++kc) {
        const int s = kc & 1;
        const uint32_t AH = sb + SM_AH(s), AL = sb + SM_AL(s);
        const uint32_t BS = sb + SM_B(s);

#pragma unroll
        for (int ks = 0; ks < 4; ++ks) {
            const uint32_t kbyte = (uint32_t)(ks * 32);
            uint32_t ah[4][4], al[4][4];
#pragma unroll
            for (int mi = 0; mi < 4; ++mi) {
                const int r = arow + mi * 16;
                uint32_t sw = ((uint32_t)(r * 128) + kbyte + acb) ^ (((uint32_t)(r & 7)) << 4);
                LDMX4(ah[mi], AH + sw);
                LDMX4(al[mi], AL + sw);
            }
            uint32_t b[8][2];
#pragma unroll
            for (int ni = 0; ni < 8; ++ni) {
                const int r = brow0 + ni * 8;
                uint32_t sw = ((uint32_t)(r * 128) + kbyte + bcb) ^ (((uint32_t)(r & 7)) << 4);
                LDMX2(b[ni], BS + sw);
            }
#pragma unroll
            for (int mi = 0; mi < 4; ++mi)
#pragma unroll
                for (int ni = 0; ni < 8; ++ni)
                    MMA16816H(c[mi][ni], ah[mi], b[ni]);
#pragma unroll
            for (int mi = 0; mi < 4; ++mi)
#pragma unroll
                for (int ni = 0; ni < 8; ++ni)
                    MMA16816H(c[mi][ni], al[mi], b[ni]);
        }

        if (kc < 3) {
            __syncthreads();                 // all warps done reading stage s
            if (kc < 2) loadB(s, kc + 2);    // refill just-freed B stage
            splitA(s ^ 1, xr);               // A(kc+1) regs -> smem
            if (kc < 2) loadAreg(kc + 2, xr);
            if (kc < 2) { CP_WAIT(1); } else { CP_WAIT(0); }  // B(kc+1) arrived
            __syncthreads();
        }
    }

    // ---- epilogue: store z + deterministic fused column stats ----
    const int gr = lane >> 2;
    const int qc = (lane & 3) * 2;
    const int mW = rowBase + warp_m * 64;
    const int nW = warp_n * 64;
    const int prow = blockIdx.x * 2 + warp_m;

#pragma unroll
    for (int ni = 0; ni < 8; ++ni) {
        float s0 = 0.f, s1 = 0.f, q0 = 0.f, q1 = 0.f;
        const int n0 = nW + ni * 8 + qc;
#pragma unroll
        for (int mi = 0; mi < 4; ++mi) {
            const float* cf = c[mi][ni];
            const int m0 = mW + mi * 16 + gr;
            *(float2*)(g_z + (size_t)m0 * CC + n0)       = make_float2(cf[0], cf[1]);
            *(float2*)(g_z + (size_t)(m0 + 8) * CC + n0) = make_float2(cf[2], cf[3]);
            s0 += cf[0] + cf[2];
            s1 += cf[1] + cf[3];
            q0 += cf[0] * cf[0] + cf[2] * cf[2];
            q1 += cf[1] * cf[1] + cf[3] * cf[3];
        }
#pragma unroll
        for (int off = 4; off < 32; off <<= 1) {
            s0 += __shfl_xor_sync(0xFFFFFFFFu, s0, off);
            s1 += __shfl_xor_sync(0xFFFFFFFFu, s1, off);
            q0 += __shfl_xor_sync(0xFFFFFFFFu, q0, off);
            q1 += __shfl_xor_sync(0xFFFFFFFFu, q1, off);
        }
        if (lane < 4) {
            g_psum[prow * CC + n0]     = s0;
            g_psum[prow * CC + n0 + 1] = s1;
            g_psq [prow * CC + n0]     = q0;
            g_psq [prow * CC + n0 + 1] = q1;
        }
    }
}

// ---------------------------------------------------------------------------
// Kernel 3: finalize mean / inv-std. grid(4 batches, 8 channel-groups) x 256.
// Coalesced 2-D load (tx = channel, ty = partial group) + smem tree: one
// latency wave instead of 64 serial strided loads.
// ---------------------------------------------------------------------------
__global__ void k_finalize() {
    const int b  = blockIdx.x;
    const int cg = blockIdx.y;
    const int tx = threadIdx.x & 31;
    const int ty = threadIdx.x >> 5;      // 0..7
    const int c  = cg * 32 + tx;

    float s = 0.f, s2 = 0.f;
#pragma unroll
    for (int i = 0; i < 8; ++i) {
        const int p = ty * 8 + i;
        s  += g_psum[(b * 64 + p) * CC + c];
        s2 += g_psq [(b * 64 + p) * CC + c];
    }
    __shared__ float rs[8][32], rq[8][32];
    rs[ty][tx] = s;
    rq[ty][tx] = s2;
    __syncthreads();
    if (ty == 0) {
#pragma unroll
        for (int i = 1; i < 8; ++i) { s += rs[i][tx]; s2 += rq[i][tx]; }
        const float mean = s * (1.f / NN);
        const float var  = s2 * (1.f / NN) - mean * mean;
        g_mean[b * CC + c] = mean;
        g_inv [b * CC + c] = rsqrtf(var + LN_EPS);
    }
}

// ---------------------------------------------------------------------------
// Kernel 4: epilogue  out = relu((z-mean)*inv*scale + bias) + x  (flat grid)
// ---------------------------------------------------------------------------
__global__ void __launch_bounds__(256)
k_epi(const float* __restrict__ X, const float* __restrict__ scale,
      const float* __restrict__ bias, float* __restrict__ out) {
    const int idx = blockIdx.x * blockDim.x + threadIdx.x;   // float4 index
    const int c4  = idx & 63;
    const int row = idx >> 6;
    const int b   = row >> 12;

    float4 z  = ((const float4*)g_z)[idx];
    float4 x  = ((const float4*)X)[idx];
    float4 mn = ((const float4*)(g_mean + b * CC))[c4];
    float4 iv = ((const float4*)(g_inv  + b * CC))[c4];
    float4 sc = ((const float4*)scale)[c4];
    float4 bi = ((const float4*)bias)[c4];

    float4 o;
    o.x = fmaxf((z.x - mn.x) * iv.x * sc.x + bi.x, 0.f) + x.x;
    o.y = fmaxf((z.y - mn.y) * iv.y * sc.y + bi.y, 0.f) + x.y;
    o.z = fmaxf((z.z - mn.z) * iv.z * sc.z + bi.z, 0.f) + x.z;
    o.w = fmaxf((z.w - mn.w) * iv.w * sc.w + bi.w, 0.f) + x.w;
    ((float4*)out)[idx] = o;
}

// ---------------------------------------------------------------------------
// Inputs: 0=inputs 1=mask 2=Wq 3=bq 4=Wk 5=bk 6=Wv 7=bv 8=Wo 9=bo
//         10=ln_scale 11=ln_bias
// mask/Wq/bq/Wk/bk numerically irrelevant (softmax column-sum collapse);
// bv/bo cancel in the points-axis LayerNorm. All dead.
// ---------------------------------------------------------------------------
extern "C" void kernel_launch(void* const* d_in, const int* in_sizes, int n_in,
                              void* d_out, int out_size) {
    const float* x        = (const float*)d_in[0];
    const float* Wv       = (const float*)d_in[6];
    const float* Wo       = (const float*)d_in[8];
    const float* ln_scale = (const float*)d_in[10];
    const float* ln_bias  = (const float*)d_in[11];
    float* out = (float*)d_out;

    cudaFuncSetAttribute(k_gemm_mma, cudaFuncAttributeMaxDynamicSharedMemorySize, SMEM_TOTAL);

    k_prep<<<CC, CC>>>(Wv, Wo);
    k_gemm_mma<<<M_TOT / 128, 256, SMEM_TOTAL>>>(x);
    k_finalize<<<dim3(BB, 8), 256>>>();
    k_epi<<<(M_TOT * CC / 4) / 256, 256>>>(x, ln_scale, ln_bias, out);
}

// round 8
// speedup vs baseline: 1.4756x; 1.1049x over previous
#include <cuda_runtime.h>
#include <cuda_fp16.h>
#include <cstdint>

// Problem constants (fixed by the reference: B=4, N=4096, C=256)
#define BB 4
#define NN 4096
#define CC 256
#define M_TOT (BB * NN)          // 16384 rows
#define LN_EPS 1e-6f

// ---------------------------------------------------------------------------
// Scratch (static device globals; no runtime allocation allowed)
// ---------------------------------------------------------------------------
__device__ __align__(16) __half g_BT[CC * CC];   // [n][k] = fp16(Wvo[k][n])
__device__ float g_z[(size_t)M_TOT * CC];        // pre-LN activations (16.8 MB)
__device__ float g_psum[256 * CC];               // per-(64-row warp-tile) col sums
__device__ float g_psq [256 * CC];
__device__ float g_mean[BB * CC];
__device__ float g_inv[BB * CC];                 // rsqrt(var + eps)

// ---------------------------------------------------------------------------
// Warp-MMA + cp.async helpers (sm_80-era PTX: compiles at compute_103)
// ---------------------------------------------------------------------------
__device__ __forceinline__ uint32_t smem_u32(const void* p) {
    uint32_t a;
    asm("{ .reg .u64 t; cvta.to.shared.u64 t, %1; cvt.u32.u64 %0, t; }" : "=r"(a) : "l"(p));
    return a;
}
#define LDMX4(r, a) \
    asm volatile("ldmatrix.sync.aligned.m8n8.x4.shared.b16 {%0,%1,%2,%3}, [%4];" \
        : "=r"((r)[0]), "=r"((r)[1]), "=r"((r)[2]), "=r"((r)[3]) : "r"(a))
#define LDMX2(r, a) \
    asm volatile("ldmatrix.sync.aligned.m8n8.x2.shared.b16 {%0,%1}, [%2];" \
        : "=r"((r)[0]), "=r"((r)[1]) : "r"(a))
#define MMA16816H(c, a, b) \
    asm volatile("mma.sync.aligned.m16n8k16.row.col.f32.f16.f16.f32 " \
        "{%0,%1,%2,%3}, {%4,%5,%6,%7}, {%8,%9}, {%0,%1,%2,%3};" \
        : "+f"((c)[0]), "+f"((c)[1]), "+f"((c)[2]), "+f"((c)[3]) \
        : "r"((a)[0]), "r"((a)[1]), "r"((a)[2]), "r"((a)[3]), "r"((b)[0]), "r"((b)[1]))
#define CP16(dst, src) \
    asm volatile("cp.async.cg.shared.global [%0], [%1], 16;" :: "r"(dst), "l"(src))
#define CP_COMMIT() asm volatile("cp.async.commit_group;" ::: "memory")
#define CP_WAIT(n)  asm volatile("cp.async.wait_group %0;" :: "n"(n) : "memory")

// Convert 8 fp32 -> 8 fp16 packed as uint4.
__device__ __forceinline__ uint4 cvt8h(float4 a, float4 b) {
    float f[8] = {a.x, a.y, a.z, a.w, b.x, b.y, b.z, b.w};
    uint32_t h[8];
#pragma unroll
    for (int j = 0; j < 8; ++j)
        h[j] = (uint32_t)__half_as_ushort(__float2half_rn(f[j]));
    return make_uint4(h[0] | (h[1] << 16), h[2] | (h[3] << 16),
                      h[4] | (h[5] << 16), h[6] | (h[7] << 16));
}

// ---------------------------------------------------------------------------
// Kernel 1: fold weights Wvo = Wv @ Wo -> fp16, store TRANSPOSED [n][k]
// (col-major B operand for mma.row.col). Biases cancel in the points-axis
// LayerNorm and are dead.
// ---------------------------------------------------------------------------
__global__ void k_prep(const float* __restrict__ Wv, const float* __restrict__ Wo) {
    const int i = blockIdx.x;     // k index (row of Wvo)
    const int j = threadIdx.x;    // n index (col of Wvo)
    float acc = 0.f;
#pragma unroll 8
    for (int m = 0; m < CC; ++m)
        acc += Wv[i * CC + m] * Wo[m * CC + j];
    g_BT[j * CC + i] = __float2half_rn(acc);
}

// ---------------------------------------------------------------------------
// Kernel 2: fp16 warp-MMA GEMM  z = X[16384,256] @ Wvo[256,256]
// 128 CTAs x 256 thr; CTA tile 128m x 256n; warp tile 64x64.
// A, B both fp16 (2^-12 RN trunc each; combined ~1.7e-4 output rel err),
// fp32 accumulate. K in 4 chunks of 64, double-buffered: B via cp.async,
// next A chunk prefetched to regs during compute, cvt->STS between chunks.
// Fused deterministic per-warp column stats.
// smem = 2 stages x (A 16K + B 32K) = 96 KB.
// ---------------------------------------------------------------------------
#define SM_A(s) ((s) * 49152)
#define SM_B(s) ((s) * 49152 + 16384)
#define SMEM_TOTAL 98304

__global__ void __launch_bounds__(256, 1)
k_gemm_mma(const float* __restrict__ X) {
    extern __shared__ char smem[];
    const uint32_t sb = smem_u32(smem);
    const int tid = threadIdx.x;
    const int lane = tid & 31;
    const int warp = tid >> 5;
    const int warp_m = warp & 1;       // 2 warps along m (64 each)
    const int warp_n = warp >> 1;      // 4 warps along n (64 each)
    const int rowBase = blockIdx.x * 128;

    // A-load mapping: 2 threads per row, 32 fp32 each (8 float4)
    const int a_ldrow = tid >> 1;
    const int a_ldch  = (tid & 1) * 32;

    float c[4][8][4];
#pragma unroll
    for (int mi = 0; mi < 4; ++mi)
#pragma unroll
        for (int ni = 0; ni < 8; ++ni)
#pragma unroll
            for (int e = 0; e < 4; ++e) c[mi][ni][e] = 0.f;

    // B tile load: 256 n-rows x 64 k (128B/row); 8 x 16B per thread.
    auto loadB = [&](int stage, int kc) {
        const char* bp = (const char*)g_BT + (size_t)tid * 512 + kc * 128;
        const uint32_t rsw = ((uint32_t)(tid & 7)) << 4;
#pragma unroll
        for (int g = 0; g < 8; ++g) {
            uint32_t sw = ((uint32_t)(tid * 128 + g * 16)) ^ rsw;
            CP16(sb + SM_B(stage) + sw, bp + g * 16);
        }
        CP_COMMIT();
    };
    auto loadAreg = [&](int kc, float4* xr) {
        const float4* xp = (const float4*)(X + (size_t)(rowBase + a_ldrow) * CC + kc * 64 + a_ldch);
#pragma unroll
        for (int g = 0; g < 8; ++g) xr[g] = xp[g];
    };
    auto cvtA = [&](int stage, const float4* xr) {
        const uint32_t rsw = ((uint32_t)(a_ldrow & 7)) << 4;
#pragma unroll
        for (int g = 0; g < 4; ++g) {
            uint4 hv = cvt8h(xr[2 * g], xr[2 * g + 1]);
            uint32_t sw = ((uint32_t)(a_ldrow * 128 + (a_ldch + g * 8) * 2)) ^ rsw;
            *(uint4*)(smem + SM_A(stage) + sw) = hv;
        }
    };

    // ---- prologue: B0,B1 in flight; A0 converted to smem; A1 in regs ----
    float4 xr[8];
    loadB(0, 0);
    loadB(1, 1);
    loadAreg(0, xr);
    cvtA(0, xr);
    loadAreg(1, xr);
    CP_WAIT(1);            // B0 arrived
    __syncthreads();

    // ldmatrix address components
    const int arow = warp_m * 64 + (lane & 15);
    const uint32_t acb = (uint32_t)((lane >> 4) << 4);
    const int brow0 = warp_n * 64 + (lane & 7);
    const uint32_t bcb = (uint32_t)(((lane >> 3) & 1) << 4);

#pragma unroll
    for (int kc = 0; kc < 4; ++kc) {
        const int s = kc & 1;
        const uint32_t AS = sb + SM_A(s);
        const uint32_t BS = sb + SM_B(s);

#pragma unroll
        for (int ks = 0; ks < 4; ++ks) {
            const uint32_t kbyte = (uint32_t)(ks * 32);
            uint32_t a[4][4];
#pragma unroll
            for (int mi = 0; mi < 4; ++mi) {
                const int r = arow + mi * 16;
                uint32_t sw = ((uint32_t)(r * 128) + kbyte + acb) ^ (((uint32_t)(r & 7)) << 4);
                LDMX4(a[mi], AS + sw);
            }
            uint32_t b[8][2];
#pragma unroll
            for (int ni = 0; ni < 8; ++ni) {
                const int r = brow0 + ni * 8;
                uint32_t sw = ((uint32_t)(r * 128) + kbyte + bcb) ^ (((uint32_t)(r & 7)) << 4);
                LDMX2(b[ni], BS + sw);
            }
#pragma unroll
            for (int mi = 0; mi < 4; ++mi)
#pragma unroll
                for (int ni = 0; ni < 8; ++ni)
                    MMA16816H(c[mi][ni], a[mi], b[ni]);
        }

        if (kc < 3) {
            __syncthreads();                 // all warps done reading stage s
            if (kc < 2) loadB(s, kc + 2);    // refill just-freed B stage
            cvtA(s ^ 1, xr);                 // A(kc+1) regs -> smem
            if (kc < 2) loadAreg(kc + 2, xr);
            if (kc < 2) { CP_WAIT(1); } else { CP_WAIT(0); }  // B(kc+1) arrived
            __syncthreads();
        }
    }

    // ---- epilogue: store z + deterministic fused column stats ----
    const int gr = lane >> 2;
    const int qc = (lane & 3) * 2;
    const int mW = rowBase + warp_m * 64;
    const int nW = warp_n * 64;
    const int prow = blockIdx.x * 2 + warp_m;

#pragma unroll
    for (int ni = 0; ni < 8; ++ni) {
        float s0 = 0.f, s1 = 0.f, q0 = 0.f, q1 = 0.f;
        const int n0 = nW + ni * 8 + qc;
#pragma unroll
        for (int mi = 0; mi < 4; ++mi) {
            const float* cf = c[mi][ni];
            const int m0 = mW + mi * 16 + gr;
            *(float2*)(g_z + (size_t)m0 * CC + n0)       = make_float2(cf[0], cf[1]);
            *(float2*)(g_z + (size_t)(m0 + 8) * CC + n0) = make_float2(cf[2], cf[3]);
            s0 += cf[0] + cf[2];
            s1 += cf[1] + cf[3];
            q0 += cf[0] * cf[0] + cf[2] * cf[2];
            q1 += cf[1] * cf[1] + cf[3] * cf[3];
        }
#pragma unroll
        for (int off = 4; off < 32; off <<= 1) {
            s0 += __shfl_xor_sync(0xFFFFFFFFu, s0, off);
            s1 += __shfl_xor_sync(0xFFFFFFFFu, s1, off);
            q0 += __shfl_xor_sync(0xFFFFFFFFu, q0, off);
            q1 += __shfl_xor_sync(0xFFFFFFFFu, q1, off);
        }
        if (lane < 4) {
            g_psum[prow * CC + n0]     = s0;
            g_psum[prow * CC + n0 + 1] = s1;
            g_psq [prow * CC + n0]     = q0;
            g_psq [prow * CC + n0 + 1] = q1;
        }
    }
}

// ---------------------------------------------------------------------------
// Kernel 3: finalize mean / inv-std. grid(4 batches, 8 channel-groups) x 256.
// Coalesced 2-D load (tx = channel, ty = partial group) + smem tree.
// ---------------------------------------------------------------------------
__global__ void k_finalize() {
    const int b  = blockIdx.x;
    const int cg = blockIdx.y;
    const int tx = threadIdx.x & 31;
    const int ty = threadIdx.x >> 5;      // 0..7
    const int c  = cg * 32 + tx;

    float s = 0.f, s2 = 0.f;
#pragma unroll
    for (int i = 0; i < 8; ++i) {
        const int p = ty * 8 + i;
        s  += g_psum[(b * 64 + p) * CC + c];
        s2 += g_psq [(b * 64 + p) * CC + c];
    }
    __shared__ float rs[8][32], rq[8][32];
    rs[ty][tx] = s;
    rq[ty][tx] = s2;
    __syncthreads();
    if (ty == 0) {
#pragma unroll
        for (int i = 1; i < 8; ++i) { s += rs[i][tx]; s2 += rq[i][tx]; }
        const float mean = s * (1.f / NN);
        const float var  = s2 * (1.f / NN) - mean * mean;
        g_mean[b * CC + c] = mean;
        g_inv [b * CC + c] = rsqrtf(var + LN_EPS);
    }
}

// ---------------------------------------------------------------------------
// Kernel 4: epilogue  out = relu((z-mean)*inv*scale + bias) + x
// 2 independent float4 streams per thread (doubled MLP); 2048 blocks.
// ---------------------------------------------------------------------------
__global__ void __launch_bounds__(256)
k_epi(const float* __restrict__ X, const float* __restrict__ scale,
      const float* __restrict__ bias, float* __restrict__ out) {
    const int i0 = blockIdx.x * (blockDim.x * 2) + threadIdx.x;
    const int i1 = i0 + blockDim.x;

#pragma unroll
    for (int t = 0; t < 2; ++t) {
        const int idx = t == 0 ? i0 : i1;
        const int c4  = idx & 63;
        const int b   = idx >> 18;        // row>>12 with row = idx>>6

        float4 z  = ((const float4*)g_z)[idx];
        float4 x  = ((const float4*)X)[idx];
        float4 mn = ((const float4*)(g_mean + b * CC))[c4];
        float4 iv = ((const float4*)(g_inv  + b * CC))[c4];
        float4 sc = ((const float4*)scale)[c4];
        float4 bi = ((const float4*)bias)[c4];

        float4 o;
        o.x = fmaxf((z.x - mn.x) * iv.x * sc.x + bi.x, 0.f) + x.x;
        o.y = fmaxf((z.y - mn.y) * iv.y * sc.y + bi.y, 0.f) + x.y;
        o.z = fmaxf((z.z - mn.z) * iv.z * sc.z + bi.z, 0.f) + x.z;
        o.w = fmaxf((z.w - mn.w) * iv.w * sc.w + bi.w, 0.f) + x.w;
        ((float4*)out)[idx] = o;
    }
}

// ---------------------------------------------------------------------------
// Inputs: 0=inputs 1=mask 2=Wq 3=bq 4=Wk 5=bk 6=Wv 7=bv 8=Wo 9=bo
//         10=ln_scale 11=ln_bias
// mask/Wq/bq/Wk/bk numerically irrelevant (softmax column-sum collapse);
// bv/bo cancel in the points-axis LayerNorm. All dead.
// ---------------------------------------------------------------------------
extern "C" void kernel_launch(void* const* d_in, const int* in_sizes, int n_in,
                              void* d_out, int out_size) {
    const float* x        = (const float*)d_in[0];
    const float* Wv       = (const float*)d_in[6];
    const float* Wo       = (const float*)d_in[8];
    const float* ln_scale = (const float*)d_in[10];
    const float* ln_bias  = (const float*)d_in[11];
    float* out = (float*)d_out;

    cudaFuncSetAttribute(k_gemm_mma, cudaFuncAttributeMaxDynamicSharedMemorySize, SMEM_TOTAL);

    k_prep<<<CC, CC>>>(Wv, Wo);
    k_gemm_mma<<<M_TOT / 128, 256, SMEM_TOTAL>>>(x);
    k_finalize<<<dim3(BB, 8), 256>>>();
    k_epi<<<(M_TOT * CC / 8) / 256, 256>>>(x, ln_scale, ln_bias, out);
}